// round 11
// baseline (speedup 1.0000x reference)
#include <cuda_runtime.h>
#include <cuda_bf16.h>
#include <math.h>

// Problem dims (fixed for this instance)
#define NN   2048
#define BB   8
#define KK   4
#define NBK  (BB*KK)      // 32
#define NT   256          // fused row kernel block size
#define TM   256          // final kernel block size
#define CG_REG 1e-6f
#define TWOPI_D 6.283185307179586

// ---------------- scratch (device globals; no allocations allowed) ----------------
__device__ float g_cx[NBK*NN];
__device__ float g_cy[NBK*NN];
__device__ float g_u[BB*NN];
__device__ float g_alpha;

// ---------------- helpers ----------------
// Warp all-reduce: 5-level shfl butterfly (redux.sync.add.f32 is NOT supported
// by ptxas on sm_103 -- verified R10).
__device__ __forceinline__ float warpRedux(float v) {
    #pragma unroll
    for (int o = 16; o > 0; o >>= 1) v += __shfl_xor_sync(0xffffffffu, v, o);
    return v;
}

// Sum NW floats (NW multiple of 4) from 16B-aligned smem via float4 loads.
template<int NW>
__device__ __forceinline__ float sumP(const float* s) {
    float acc = 0.f;
    #pragma unroll
    for (int k = 0; k < NW/4; k++) {
        float4 v = reinterpret_cast<const float4*>(s)[k];
        acc += (v.x + v.y) + (v.z + v.w);
    }
    return acc;
}

template<int BARID, int NTHR>
__device__ __forceinline__ void barx() {
    asm volatile("bar.sync %0, %1;" :: "n"(BARID), "n"(NTHR) : "memory");
}

// Pentadiagonal opedoub apply on register-resident p (EPT consecutive elems per
// thread). Neighbors via intra-warp shfl; warp-edge values supplied in hl/hr.
template<int EPT>
__device__ __forceinline__ void stencil_apply(const float p[EPT],
    float hl0, float hl1, float hr0, float hr1,
    bool lane0, bool lane31, bool firstT, bool lastT, float st[EPT])
{
    float lm2 = __shfl_up_sync(0xffffffffu, p[EPT-2], 1);
    float lm1 = __shfl_up_sync(0xffffffffu, p[EPT-1], 1);
    float rp0 = __shfl_down_sync(0xffffffffu, p[0], 1);
    float rp1 = __shfl_down_sync(0xffffffffu, p[1], 1);
    if (lane0)  { lm2 = hl0; lm1 = hl1; }
    if (lane31) { rp0 = hr0; rp1 = hr1; }
    float wb[EPT+4];
    wb[0] = lm2; wb[1] = lm1;
    #pragma unroll
    for (int j = 0; j < EPT; j++) wb[2+j] = p[j];
    wb[EPT+2] = rp0; wb[EPT+3] = rp1;
    #pragma unroll
    for (int j = 0; j < EPT; j++)
        st[j] = wb[j] - 4.0f*wb[j+1] + 6.0f*wb[j+2] - 4.0f*wb[j+3] + wb[j+4];
    if (firstT) {
        st[0] =  2.0f*p[0] - 3.0f*p[1] + p[2];
        st[1] = -3.0f*p[0] + 6.0f*p[1] - 4.0f*p[2] + p[3];
    }
    if (lastT) {
        st[EPT-2] = p[EPT-4] - 4.0f*p[EPT-3] + 6.0f*p[EPT-2] - 3.0f*p[EPT-1];
        st[EPT-1] = p[EPT-3] - 3.0f*p[EPT-2] + 2.0f*p[EPT-1];
    }
}

// Register-resident CG for (coef*opedoub + diag(dreg)) x = rhs over NW warps,
// EPT consecutive elements per thread. 2 barriers per iteration, rsnew computed
// by explicit reduction (the one-barrier recurrence cancels catastrophically).
// edge slots: [0,1] = one-time x0 halos; [2,3] = per-iteration r halos
// (consecutive uses of each slot separated by >=2 barriers -> race-free).
template<int EPT, int NW, int BARID, bool X0Z>
__device__ void cg_reg(int lt, float coef, const float dreg[EPT],
                       const float rhs[EPT], const float x0[EPT], float xout[EPT],
                       float* sredA, float* sredB,
                       float (*edgeLo)[4], float (*edgeHi)[4])
{
    constexpr int NTHR = NW*32;
    const int lane = lt & 31, w = lt >> 5;
    const bool lane0 = (lane == 0), lane31 = (lane == 31);
    const bool firstT = (lt == 0), lastT = (lt == NTHR-1);
    float p[EPT], r[EPT], x[EPT];
    float hl0 = 0.f, hl1 = 0.f, hr0 = 0.f, hr1 = 0.f;
    float rsold;
    bool done = false;

    if (X0Z) {
        float d0 = 0.f, d1 = 0.f;
        #pragma unroll
        for (int j = 0; j < EPT; j++) {
            r[j] = rhs[j]; p[j] = rhs[j]; x[j] = 0.f;
            if (j & 1) d1 += r[j]*r[j]; else d0 += r[j]*r[j];
        }
        if (lane0)  { edgeLo[w][2] = r[0];     edgeLo[w][3] = r[1]; }
        if (lane31) { edgeHi[w][2] = r[EPT-2]; edgeHi[w][3] = r[EPT-1]; }
        float dd = warpRedux(d0 + d1);
        if (lane0) sredB[w] = dd;
        barx<BARID, NTHR>();
        rsold = sumP<NW>(sredB);
        if (lane0  && w > 0)    { hl0 = edgeHi[w-1][2]; hl1 = edgeHi[w-1][3]; }
        if (lane31 && w < NW-1) { hr0 = edgeLo[w+1][2]; hr1 = edgeLo[w+1][3]; }
    } else {
        #pragma unroll
        for (int j = 0; j < EPT; j++) { p[j] = x0[j]; x[j] = x0[j]; }
        if (lane0)  { edgeLo[w][0] = p[0];     edgeLo[w][1] = p[1]; }
        if (lane31) { edgeHi[w][0] = p[EPT-2]; edgeHi[w][1] = p[EPT-1]; }
        barx<BARID, NTHR>();
        if (lane0  && w > 0)    { hl0 = edgeHi[w-1][0]; hl1 = edgeHi[w-1][1]; }
        if (lane31 && w < NW-1) { hr0 = edgeLo[w+1][0]; hr1 = edgeLo[w+1][1]; }
        float st[EPT];
        stencil_apply<EPT>(p, hl0, hl1, hr0, hr1, lane0, lane31, firstT, lastT, st);
        float d0 = 0.f, d1 = 0.f;
        #pragma unroll
        for (int j = 0; j < EPT; j++) {
            r[j] = rhs[j] - (coef*st[j] + dreg[j]*p[j]);
            if (j & 1) d1 += r[j]*r[j]; else d0 += r[j]*r[j];
            p[j] = r[j];
        }
        if (lane0)  { edgeLo[w][2] = r[0];     edgeLo[w][3] = r[1]; }
        if (lane31) { edgeHi[w][2] = r[EPT-2]; edgeHi[w][3] = r[EPT-1]; }
        float dd = warpRedux(d0 + d1);
        if (lane0) sredB[w] = dd;
        barx<BARID, NTHR>();
        rsold = sumP<NW>(sredB);
        if (lane0  && w > 0)    { hl0 = edgeHi[w-1][2]; hl1 = edgeHi[w-1][3]; }
        if (lane31 && w < NW-1) { hr0 = edgeLo[w+1][2]; hr1 = edgeLo[w+1][3]; }
    }

    for (int it = 0; it < 30; it++) {
        float st[EPT], Ap[EPT];
        stencil_apply<EPT>(p, hl0, hl1, hr0, hr1, lane0, lane31, firstT, lastT, st);
        float d0 = 0.f, d1 = 0.f;
        #pragma unroll
        for (int j = 0; j < EPT; j++) {
            Ap[j] = coef*st[j] + dreg[j]*p[j];
            if (j & 1) d1 += p[j]*Ap[j]; else d0 += p[j]*Ap[j];
        }
        float dd = warpRedux(d0 + d1);
        if (lane0) sredA[w] = dd;
        barx<BARID, NTHR>();
        float pAp = sumP<NW>(sredA);
        float a = __fdividef(rsold, pAp + 1e-12f);
        if (!done) {
            #pragma unroll
            for (int j = 0; j < EPT; j++) { x[j] += a*p[j]; r[j] -= a*Ap[j]; }
        }
        float e0 = 0.f, e1 = 0.f;
        #pragma unroll
        for (int j = 0; j < EPT; j++) {
            if (j & 1) e1 += r[j]*r[j]; else e0 += r[j]*r[j];
        }
        float dd2 = warpRedux(e0 + e1);
        if (lane0)  { sredB[w] = dd2; edgeLo[w][2] = r[0]; edgeLo[w][3] = r[1]; }
        if (lane31) { edgeHi[w][2] = r[EPT-2]; edgeHi[w][3] = r[EPT-1]; }
        barx<BARID, NTHR>();
        float rsnew = sumP<NW>(sredB);
        bool done1 = done || (sqrtf(rsnew) < 1e-6f);
        float bta = __fdividef(rsnew, rsold + 1e-12f);
        if (!done1) {
            #pragma unroll
            for (int j = 0; j < EPT; j++) p[j] = r[j] + bta*p[j];
            if (lane0  && w > 0)    { hl0 = edgeHi[w-1][2] + bta*hl0; hl1 = edgeHi[w-1][3] + bta*hl1; }
            if (lane31 && w < NW-1) { hr0 = edgeLo[w+1][2] + bta*hr0; hr1 = edgeLo[w+1][3] + bta*hr1; }
            rsold = rsnew;
        }
        done = done1;
    }
    #pragma unroll
    for (int j = 0; j < EPT; j++) xout[j] = x[j];
}

// cumulative trapezoid over NN with NTHR threads (NN/NTHR consecutive elems
// per thread), double accum, named barrier BARID (group-local).
template<int NTHR, int BARID>
__device__ void cumtz(int lt, const float* y, float dxf, double* warpoff, double* Pout) {
    constexpr int EPT2 = NN/NTHR, NW = NTHR/32;
    int lane = lt & 31, w = lt >> 5, base = lt*EPT2;
    double acc = 0.0, pre[EPT2];
    #pragma unroll
    for (int m = 0; m < EPT2; m++) {
        int j = base + m;
        float a = (j < NN-1) ? ((y[j] + y[j+1]) * (0.5f*dxf)) : 0.0f;
        pre[m] = acc; acc += (double)a;
    }
    double v = acc;
    #pragma unroll
    for (int o = 1; o < 32; o <<= 1) {
        double n = __shfl_up_sync(0xffffffffu, v, o);
        if (lane >= o) v += n;
    }
    if (lane == 31) warpoff[w] = v;
    double excl = v - acc;
    barx<BARID, NTHR>();
    if (lt == 0) {
        double run = 0.0;
        #pragma unroll
        for (int ww = 0; ww < NW; ww++) { double tmp = warpoff[ww]; warpoff[ww] = run; run += tmp; }
    }
    barx<BARID, NTHR>();
    double off = warpoff[w] + excl;
    #pragma unroll
    for (int m = 0; m < EPT2; m++) Pout[m] = off + pre[m];
}

// ---------------- K1: fused per-row pipeline (MLP folded in) ----------------
// 32 blocks x 256 threads.
// warps 0-3: phase cumtrapz(eIF) -> cos/sin (named bar 3)
// warps 4-7: hyperparameter MLP (identical in every block; named bar 4)
// then: u projection -> concurrent x/y CG (128 thr each, bars 1/2) ->
// smooth CG (256 thr, bar 0) -> epilogue.
__global__ void __launch_bounds__(NT) row_kernel(
    const float* s, const float* eIF, const float* xm, const float* ym,
    const float* sum_x, const float* sum_y, const float* lamuda,
    const int* mode_mask, const float* fs_p, const float* var_p,
    const float* init_freqs, const float* alpha_p, const float* beta_p,
    const float* fe_w1, const float* fe_b1, const float* fe_w2, const float* fe_b2,
    const float* pr_w1, const float* pr_b1, const float* pr_w2, const float* pr_b2,
    const float* pr_w3, const float* pr_b3, const float* iter_w, const int* iter_p,
    float* out_eIF, float* out_xm, float* out_ym, float* out_scal)
{
    __shared__ float bufA[NN];   // cos  -> xs solution
    __shared__ float bufB[NN];   // sin  -> ys solution
    __shared__ float bufC[NN];   // MLP scratch -> new_eIF staging
    __shared__ double warpoff[8];
    __shared__ __align__(16) float sredAX[4], sredBX[4], sredAY[4], sredBY[4];
    __shared__ __align__(16) float sredSA[8], sredSB[8], sredF[8];
    __shared__ float eXLo[4][4], eXHi[4][4];
    __shared__ float eYLo[4][4], eYHi[4][4];
    __shared__ float eSLo[8][4], eSHi[8][4];
    __shared__ float sAB[4];     // [na, nb, betathr, bt]

    const int row = blockIdx.x, t = threadIdx.x;
    const int b = row / KK, ro = row*NN, bo = b*NN;
    const float dxf = 1.0f / (*fs_p);

    if (t < 128) {
        // ---- phase half (warps 0-3) ----
        double P[16];
        cumtz<128, 3>(t, eIF + ro, dxf, warpoff, P);
        int base = t*16;
        #pragma unroll
        for (int m = 0; m < 16; m++) {
            double frac = P[m] - floor(P[m]);
            float ph = (float)(frac * TWOPI_D);
            float sn, cs;
            __sincosf(ph, &sn, &cs);
            bufA[base+m] = cs;
            bufB[base+m] = sn;
        }
    } else {
        // ---- MLP half (warps 4-7, lt in 0..127) ----
        int lt = t - 128;
        float* m_avg = bufC;          // 8
        float* m_h1  = bufC + 8;      // 256  [b*32+j]
        float* m_h2  = bufC + 264;    // 144  [b*18+j]
        float* m_z1  = bufC + 408;    // 512  [b*64+j]
        float* m_z2  = bufC + 920;    // 256  [b*32+j]
        float* m_res = bufC + 1176;   // 16   [b*2+j]
        float alpha = *alpha_p, beta = *beta_p;
        if (lt == 0) {
            int it = *iter_p;
            sAB[3] = (float)pow(10.0, (double)it/36.0 - 10.0);
        }
        if (lt < BB) {
            float a = 0.f;
            #pragma unroll
            for (int k = 0; k < KK; k++) a += init_freqs[lt*KK + k];
            m_avg[lt] = a / (float)KK;
        }
        barx<4, 128>();
        #pragma unroll
        for (int idx = lt; idx < BB*32; idx += 128) { // fe1: 8x32
            int bb2 = idx >> 5, j = idx & 31;
            float v = fe_w1[j]*m_avg[bb2] + fe_b1[j];
            m_h1[bb2*32 + j] = v > 0.f ? v : 0.f;
        }
        barx<4, 128>();
        {   // fe2: 8x16 = 128 outputs, one per thread
            int bb2 = lt >> 4, j = lt & 15;
            float acc = fe_b2[j];
            #pragma unroll
            for (int k = 0; k < 32; k++) acc += fe_w2[j*32 + k]*m_h1[bb2*32 + k];
            m_h2[bb2*18 + j] = acc > 0.f ? acc : 0.f;
        }
        if (lt < BB) {
            m_h2[lt*18 + 16] = alpha;
            m_h2[lt*18 + 17] = beta;
        }
        barx<4, 128>();
        #pragma unroll
        for (int idx = lt; idx < BB*64; idx += 128) { // pr1: 8x64
            int bb2 = idx >> 6, j = idx & 63;
            float acc = pr_b1[j];
            #pragma unroll
            for (int k = 0; k < 18; k++) acc += pr_w1[j*18 + k]*m_h2[bb2*18 + k];
            m_z1[bb2*64 + j] = acc > 0.f ? acc : 0.f;
        }
        barx<4, 128>();
        #pragma unroll
        for (int idx = lt; idx < BB*32; idx += 128) { // pr2: 8x32
            int bb2 = idx >> 5, j = idx & 31;
            float acc = pr_b2[j];
            #pragma unroll
            for (int k = 0; k < 64; k++) acc += pr_w2[j*64 + k]*m_z1[bb2*64 + k];
            m_z2[bb2*32 + j] = acc > 0.f ? acc : 0.f;
        }
        barx<4, 128>();
        if (lt < BB*2) { // pr3 + tanh + scaling
            int bb2 = lt >> 1, j = lt & 1;
            float acc = pr_b3[j];
            #pragma unroll
            for (int k = 0; k < 32; k++) acc += pr_w3[j*32 + k]*m_z2[bb2*32 + k];
            float itf = (float)(*iter_p);
            float fac = 1.0f / (1.0f + expf(-(*iter_w)*itf));
            m_res[bb2*2 + j] = tanhf(acc) * fac * 0.1f;
        }
        barx<4, 128>();
        if (lt == 0) {
            float m0 = 0.f, m1 = 0.f;
            #pragma unroll
            for (int bb2 = 0; bb2 < BB; bb2++) { m0 += m_res[bb2*2]; m1 += m_res[bb2*2+1]; }
            m0 /= (float)BB; m1 /= (float)BB;
            float na = fminf(fmaxf(alpha + m0*alpha, 1e-6f), 0.01f);
            float nb = fminf(fmaxf(beta + m1*beta, 1e-6f), 0.1f);
            float bthr = fminf(sAB[3], nb);
            sAB[0] = na; sAB[1] = nb; sAB[2] = bthr;
            g_alpha = na;                     // same value from every block (benign)
            if (row == 0) { out_scal[0] = na; out_scal[1] = nb; }
        }
    }
    __syncthreads();

    const float na = sAB[0];
    const float bthr = sAB[2];

    // --- ||v|| for the norm-ball projection (u = scale*v) ---
    {
        float d0 = 0.f, d1 = 0.f;
        int b8 = t*8;
        #pragma unroll
        for (int m = 0; m < 8; m++) {
            int i = b8 + m;
            float v = s[bo+i] - sum_x[bo+i] - sum_y[bo+i] - lamuda[bo+i]/na;
            if (m & 1) d1 += v*v; else d0 += v*v;
        }
        float dd = warpRedux(d0 + d1);
        if ((t & 31) == 0) sredF[t >> 5] = dd;
    }
    __syncthreads();
    float n2 = sumP<8>(sredF);
    float nrm = sqrtf(n2);
    float e = sqrtf((float)NN * (*var_p));
    float scale = (nrm > e) ? (e / fmaxf(nrm, 1e-30f)) : 1.0f;

    // --- x/y CG setup (16 consecutive elems per thread within each half) ---
    const bool isY = (t >= 128);
    const int lt = t & 127;
    float dreg[16], rhs[16], x0v[16], sol[16];
    {
        int base = lt*16;
        #pragma unroll
        for (int j = 0; j < 16; j++) {
            int i = base + j;
            float c = bufA[i], sn = bufB[i];
            float xmv = xm[ro+i], ymv = ym[ro+i];
            float v = s[bo+i] - sum_x[bo+i] - sum_y[bo+i] - lamuda[bo+i]/na;
            float u = scale * v;
            float resid = v - u + xmv*c + ymv*sn;
            if (!isY) {
                dreg[j] = c*c + CG_REG;  rhs[j] = c*resid;  x0v[j] = xmv;
                g_u[bo+i] = u;   // x-half covers all i; dup across k-CTAs identical
            } else {
                dreg[j] = sn*sn + CG_REG; rhs[j] = sn*resid; x0v[j] = ymv;
            }
        }
    }
    __syncthreads();   // bufA/bufB reads done before solutions overwrite them
    float coef = 2.0f / na;
    if (!isY)
        cg_reg<16,4,1,false>(lt, coef, dreg, rhs, x0v, sol, sredAX, sredBX, eXLo, eXHi);
    else
        cg_reg<16,4,2,false>(lt, coef, dreg, rhs, x0v, sol, sredAY, sredBY, eYLo, eYHi);
    {
        int base = lt*16;
        float* dst = isY ? bufB : bufA;
        #pragma unroll
        for (int j = 0; j < 16; j++) dst[base+j] = sol[j];
    }
    __syncthreads();

    // --- smooth CG (full block, 8 consecutive elems per thread) ---
    float dregS[8], rhsS[8], zero8[8], solS[8];
    {
        int base = t*8;
        const float TWOPIF = 6.2831853071795864769f;
        #pragma unroll
        for (int m = 0; m < 8; m++) {
            int i = base + m;
            float xv = bufA[i], yv = bufB[i];
            float xb = (i == 0)    ? (bufA[1]-bufA[0]) / dxf
                     : (i == NN-1) ? (bufA[NN-1]-bufA[NN-2]) / dxf
                     : (bufA[i+1]-bufA[i-1]) / (2.0f*dxf);
            float yb = (i == 0)    ? (bufB[1]-bufB[0]) / dxf
                     : (i == NN-1) ? (bufB[NN-1]-bufB[NN-2]) / dxf
                     : (bufB[i+1]-bufB[i-1]) / (2.0f*dxf);
            float denom = xv*xv + yv*yv + 1e-12f;
            rhsS[m]  = (xv*yb - yv*xb) / (denom * TWOPIF);
            dregS[m] = 1.0f + CG_REG;
            zero8[m] = 0.f;
        }
    }
    float coefS = 2.0f / bthr;
    cg_reg<8,8,0,true>(t, coefS, dregS, rhsS, zero8, solS, sredSA, sredSB, eSLo, eSHi);

    // --- epilogue: outputs + new-phase contributions ---
    bool active = (mode_mask[row] != 0);
    float maskf = active ? 1.0f : 0.0f;
    float nxm[8], nym[8];
    {
        int base = t*8;
        #pragma unroll
        for (int m = 0; m < 8; m++) {
            int i = base + m;
            float ne = active ? (eIF[ro+i] - 0.5f*solS[m]) : eIF[ro+i];
            out_eIF[ro+i] = ne;
            nxm[m] = active ? bufA[i] : xm[ro+i];
            nym[m] = active ? bufB[i] : ym[ro+i];
            out_xm[ro+i] = nxm[m];
            out_ym[ro+i] = nym[m];
            bufC[i] = ne;
        }
    }
    __syncthreads();
    double P2[8];
    cumtz<256, 0>(t, bufC, dxf, warpoff, P2);
    {
        int base = t*8;
        #pragma unroll
        for (int m = 0; m < 8; m++) {
            int i = base + m;
            double frac = P2[m] - floor(P2[m]);
            float ph = (float)(frac * TWOPI_D);
            float sn, cs;
            __sincosf(ph, &sn, &cs);
            g_cx[ro+i] = maskf * nxm[m] * cs;
            g_cy[ro+i] = maskf * nym[m] * sn;
        }
    }
}

// ---------------- K2: bsx/bsy sums over K + new lamuda (64 blocks) ----------------
__global__ void __launch_bounds__(TM) final_kernel(
    const float* s, const float* lamuda, float* out_bsx, float* out_bsy, float* out_lam)
{
    int b = blockIdx.x >> 3, seg = blockIdx.x & 7, t = threadIdx.x;
    int i = seg*TM + t;
    float na = g_alpha;
    float bx = 0.f, by = 0.f;
    #pragma unroll
    for (int k = 0; k < KK; k++) {
        bx += g_cx[(b*KK + k)*NN + i];
        by += g_cy[(b*KK + k)*NN + i];
    }
    out_bsx[b*NN + i] = bx;
    out_bsy[b*NN + i] = by;
    out_lam[b*NN + i] = lamuda[b*NN + i] + na * (g_u[b*NN + i] + bx + by - s[b*NN + i]);
}

// ---------------- launch ----------------
extern "C" void kernel_launch(void* const* d_in, const int* in_sizes, int n_in,
                              void* d_out, int out_size) {
    const float* s          = (const float*)d_in[0];
    const float* eIF        = (const float*)d_in[1];
    const float* xm         = (const float*)d_in[2];
    const float* ym         = (const float*)d_in[3];
    const float* sum_x      = (const float*)d_in[4];
    const float* sum_y      = (const float*)d_in[5];
    const float* lamuda     = (const float*)d_in[6];
    const float* init_freqs = (const float*)d_in[7];
    const int*   mode_mask  = (const int*)d_in[8];
    const float* alpha      = (const float*)d_in[9];
    const float* beta       = (const float*)d_in[10];
    const float* var        = (const float*)d_in[11];
    const float* fs         = (const float*)d_in[12];
    const int*   iteration  = (const int*)d_in[13];
    const float* fe_w1      = (const float*)d_in[14];
    const float* fe_b1      = (const float*)d_in[15];
    const float* fe_w2      = (const float*)d_in[16];
    const float* fe_b2      = (const float*)d_in[17];
    const float* pr_w1      = (const float*)d_in[18];
    const float* pr_b1      = (const float*)d_in[19];
    const float* pr_w2      = (const float*)d_in[20];
    const float* pr_b2      = (const float*)d_in[21];
    const float* pr_w3      = (const float*)d_in[22];
    const float* pr_b3      = (const float*)d_in[23];
    const float* iter_w     = (const float*)d_in[24];

    float* out = (float*)d_out;
    const int BKN = NBK * NN;   // 65536
    const int BN  = BB * NN;    // 16384
    float* o_eIF  = out;
    float* o_xm   = out + BKN;
    float* o_ym   = out + 2*BKN;
    float* o_bsx  = out + 3*BKN;
    float* o_bsy  = o_bsx + BN;
    float* o_lam  = o_bsy + BN;
    float* o_scal = o_lam + BN;   // [new_alpha, new_beta]

    row_kernel<<<NBK, NT>>>(s, eIF, xm, ym, sum_x, sum_y, lamuda, mode_mask,
                            fs, var, init_freqs, alpha, beta,
                            fe_w1, fe_b1, fe_w2, fe_b2,
                            pr_w1, pr_b1, pr_w2, pr_b2, pr_w3, pr_b3,
                            iter_w, iteration,
                            o_eIF, o_xm, o_ym, o_scal);
    final_kernel<<<BB*8, TM>>>(s, lamuda, o_bsx, o_bsy, o_lam);
}

// round 12
// speedup vs baseline: 1.6403x; 1.6403x over previous
#include <cuda_runtime.h>
#include <cuda_bf16.h>
#include <math.h>

// Problem dims (fixed for this instance)
#define NN   2048
#define BB   8
#define KK   4
#define NBK  (BB*KK)      // 32
#define NT   512          // fused row kernel block size
#define TM   256          // final kernel block size
#define CG_REG 1e-6f
#define TWOPI_D 6.283185307179586

// ---------------- scratch (device globals; no allocations allowed) ----------------
__device__ float g_cx[NBK*NN];
__device__ float g_cy[NBK*NN];
__device__ float g_u[BB*NN];
__device__ float g_alpha;

// ---------------- helpers ----------------
// Warp all-reduce: 5-level shfl butterfly (redux.sync.add.f32 NOT supported on sm_103).
__device__ __forceinline__ float warpRedux(float v) {
    #pragma unroll
    for (int o = 16; o > 0; o >>= 1) v += __shfl_xor_sync(0xffffffffu, v, o);
    return v;
}

// Sum NW floats (NW multiple of 4) from 16B-aligned smem via float4 loads.
template<int NW>
__device__ __forceinline__ float sumP(const float* s) {
    float acc = 0.f;
    #pragma unroll
    for (int k = 0; k < NW/4; k++) {
        float4 v = reinterpret_cast<const float4*>(s)[k];
        acc += (v.x + v.y) + (v.z + v.w);
    }
    return acc;
}

template<int BARID, int NTHR>
__device__ __forceinline__ void barx() {
    asm volatile("bar.sync %0, %1;" :: "n"(BARID), "n"(NTHR) : "memory");
}

// Pentadiagonal opedoub apply on register-resident p (EPT consecutive elems per
// thread). Neighbors via intra-warp shfl; warp-edge values supplied in hl/hr.
template<int EPT>
__device__ __forceinline__ void stencil_apply(const float p[EPT],
    float hl0, float hl1, float hr0, float hr1,
    bool lane0, bool lane31, bool firstT, bool lastT, float st[EPT])
{
    float lm2 = __shfl_up_sync(0xffffffffu, p[EPT-2], 1);
    float lm1 = __shfl_up_sync(0xffffffffu, p[EPT-1], 1);
    float rp0 = __shfl_down_sync(0xffffffffu, p[0], 1);
    float rp1 = __shfl_down_sync(0xffffffffu, p[1], 1);
    if (lane0)  { lm2 = hl0; lm1 = hl1; }
    if (lane31) { rp0 = hr0; rp1 = hr1; }
    float wb[EPT+4];
    wb[0] = lm2; wb[1] = lm1;
    #pragma unroll
    for (int j = 0; j < EPT; j++) wb[2+j] = p[j];
    wb[EPT+2] = rp0; wb[EPT+3] = rp1;
    #pragma unroll
    for (int j = 0; j < EPT; j++)
        st[j] = wb[j] - 4.0f*wb[j+1] + 6.0f*wb[j+2] - 4.0f*wb[j+3] + wb[j+4];
    if (firstT) {
        st[0] =  2.0f*p[0] - 3.0f*p[1] + p[2];
        st[1] = -3.0f*p[0] + 6.0f*p[1] - 4.0f*p[2] + p[3];
    }
    if (lastT) {
        st[EPT-2] = p[EPT-4] - 4.0f*p[EPT-3] + 6.0f*p[EPT-2] - 3.0f*p[EPT-1];
        st[EPT-1] = p[EPT-3] - 3.0f*p[EPT-2] + 2.0f*p[EPT-1];
    }
}

// Register-resident CG for (coef*opedoub + diag(dreg)) x = rhs over NW warps,
// EPT consecutive elements per thread (EPT<=8: register-budget ceiling,
// EPT=16 spills -- verified R11). 2 barriers/iter; explicit rsnew reduction
// (one-barrier recurrence cancels catastrophically -- verified R8).
// edge slots: [0,1] = one-time x0 halos; [2,3] = per-iteration r halos
// (consecutive uses separated by >=2 barriers -> race-free).
template<int EPT, int NW, int BARID, bool X0Z>
__device__ void cg_reg(int lt, float coef, const float dreg[EPT],
                       const float rhs[EPT], const float x0[EPT], float xout[EPT],
                       float* sredA, float* sredB,
                       float (*edgeLo)[4], float (*edgeHi)[4])
{
    constexpr int NTHR = NW*32;
    const int lane = lt & 31, w = lt >> 5;
    const bool lane0 = (lane == 0), lane31 = (lane == 31);
    const bool firstT = (lt == 0), lastT = (lt == NTHR-1);
    float p[EPT], r[EPT], x[EPT];
    float hl0 = 0.f, hl1 = 0.f, hr0 = 0.f, hr1 = 0.f;
    float rsold;
    bool done = false;

    if (X0Z) {
        float d0 = 0.f, d1 = 0.f;
        #pragma unroll
        for (int j = 0; j < EPT; j++) {
            r[j] = rhs[j]; p[j] = rhs[j]; x[j] = 0.f;
            if (j & 1) d1 += r[j]*r[j]; else d0 += r[j]*r[j];
        }
        if (lane0)  { edgeLo[w][2] = r[0];     edgeLo[w][3] = r[1]; }
        if (lane31) { edgeHi[w][2] = r[EPT-2]; edgeHi[w][3] = r[EPT-1]; }
        float dd = warpRedux(d0 + d1);
        if (lane0) sredB[w] = dd;
        barx<BARID, NTHR>();
        rsold = sumP<NW>(sredB);
        if (lane0  && w > 0)    { hl0 = edgeHi[w-1][2]; hl1 = edgeHi[w-1][3]; }
        if (lane31 && w < NW-1) { hr0 = edgeLo[w+1][2]; hr1 = edgeLo[w+1][3]; }
    } else {
        #pragma unroll
        for (int j = 0; j < EPT; j++) { p[j] = x0[j]; x[j] = x0[j]; }
        if (lane0)  { edgeLo[w][0] = p[0];     edgeLo[w][1] = p[1]; }
        if (lane31) { edgeHi[w][0] = p[EPT-2]; edgeHi[w][1] = p[EPT-1]; }
        barx<BARID, NTHR>();
        if (lane0  && w > 0)    { hl0 = edgeHi[w-1][0]; hl1 = edgeHi[w-1][1]; }
        if (lane31 && w < NW-1) { hr0 = edgeLo[w+1][0]; hr1 = edgeLo[w+1][1]; }
        float st[EPT];
        stencil_apply<EPT>(p, hl0, hl1, hr0, hr1, lane0, lane31, firstT, lastT, st);
        float d0 = 0.f, d1 = 0.f;
        #pragma unroll
        for (int j = 0; j < EPT; j++) {
            r[j] = rhs[j] - (coef*st[j] + dreg[j]*p[j]);
            if (j & 1) d1 += r[j]*r[j]; else d0 += r[j]*r[j];
            p[j] = r[j];
        }
        if (lane0)  { edgeLo[w][2] = r[0];     edgeLo[w][3] = r[1]; }
        if (lane31) { edgeHi[w][2] = r[EPT-2]; edgeHi[w][3] = r[EPT-1]; }
        float dd = warpRedux(d0 + d1);
        if (lane0) sredB[w] = dd;
        barx<BARID, NTHR>();
        rsold = sumP<NW>(sredB);
        if (lane0  && w > 0)    { hl0 = edgeHi[w-1][2]; hl1 = edgeHi[w-1][3]; }
        if (lane31 && w < NW-1) { hr0 = edgeLo[w+1][2]; hr1 = edgeLo[w+1][3]; }
    }

    for (int it = 0; it < 30; it++) {
        float st[EPT], Ap[EPT];
        stencil_apply<EPT>(p, hl0, hl1, hr0, hr1, lane0, lane31, firstT, lastT, st);
        float d0 = 0.f, d1 = 0.f;
        #pragma unroll
        for (int j = 0; j < EPT; j++) {
            Ap[j] = coef*st[j] + dreg[j]*p[j];
            if (j & 1) d1 += p[j]*Ap[j]; else d0 += p[j]*Ap[j];
        }
        float dd = warpRedux(d0 + d1);
        if (lane0) sredA[w] = dd;
        barx<BARID, NTHR>();
        float pAp = sumP<NW>(sredA);
        float a = __fdividef(rsold, pAp + 1e-12f);
        if (!done) {
            #pragma unroll
            for (int j = 0; j < EPT; j++) { x[j] += a*p[j]; r[j] -= a*Ap[j]; }
        }
        float e0 = 0.f, e1 = 0.f;
        #pragma unroll
        for (int j = 0; j < EPT; j++) {
            if (j & 1) e1 += r[j]*r[j]; else e0 += r[j]*r[j];
        }
        float dd2 = warpRedux(e0 + e1);
        if (lane0)  { sredB[w] = dd2; edgeLo[w][2] = r[0]; edgeLo[w][3] = r[1]; }
        if (lane31) { edgeHi[w][2] = r[EPT-2]; edgeHi[w][3] = r[EPT-1]; }
        barx<BARID, NTHR>();
        float rsnew = sumP<NW>(sredB);
        bool done1 = done || (sqrtf(rsnew) < 1e-6f);
        float bta = __fdividef(rsnew, rsold + 1e-12f);
        if (!done1) {
            #pragma unroll
            for (int j = 0; j < EPT; j++) p[j] = r[j] + bta*p[j];
            if (lane0  && w > 0)    { hl0 = edgeHi[w-1][2] + bta*hl0; hl1 = edgeHi[w-1][3] + bta*hl1; }
            if (lane31 && w < NW-1) { hr0 = edgeLo[w+1][2] + bta*hr0; hr1 = edgeLo[w+1][3] + bta*hr1; }
            rsold = rsnew;
        }
        done = done1;
    }
    #pragma unroll
    for (int j = 0; j < EPT; j++) xout[j] = x[j];
}

// cumulative trapezoid over NN with NTHR threads (NN/NTHR consecutive elems
// per thread), double accum, named barrier BARID (group-local).
template<int NTHR, int BARID>
__device__ void cumtz(int lt, const float* y, float dxf, double* warpoff, double* Pout) {
    constexpr int EPT2 = NN/NTHR, NW = NTHR/32;
    int lane = lt & 31, w = lt >> 5, base = lt*EPT2;
    double acc = 0.0, pre[EPT2];
    #pragma unroll
    for (int m = 0; m < EPT2; m++) {
        int j = base + m;
        float a = (j < NN-1) ? ((y[j] + y[j+1]) * (0.5f*dxf)) : 0.0f;
        pre[m] = acc; acc += (double)a;
    }
    double v = acc;
    #pragma unroll
    for (int o = 1; o < 32; o <<= 1) {
        double n = __shfl_up_sync(0xffffffffu, v, o);
        if (lane >= o) v += n;
    }
    if (lane == 31) warpoff[w] = v;
    double excl = v - acc;
    barx<BARID, NTHR>();
    if (lt == 0) {
        double run = 0.0;
        #pragma unroll
        for (int ww = 0; ww < NW; ww++) { double tmp = warpoff[ww]; warpoff[ww] = run; run += tmp; }
    }
    barx<BARID, NTHR>();
    double off = warpoff[w] + excl;
    #pragma unroll
    for (int m = 0; m < EPT2; m++) Pout[m] = off + pre[m];
}

// ---------------- K1: fused per-row pipeline (MLP folded in) ----------------
// 32 blocks x 512 threads.
// warps 0-7:  phase cumtrapz(eIF) -> cos/sin (named bar 3)
// warps 8-15: hyperparameter MLP (identical in every block; named bar 4)
// then: u projection -> concurrent x/y CG (256 thr each, bars 1/2) ->
// smooth CG (512 thr, bar 0) -> epilogue.
__global__ void __launch_bounds__(NT) row_kernel(
    const float* s, const float* eIF, const float* xm, const float* ym,
    const float* sum_x, const float* sum_y, const float* lamuda,
    const int* mode_mask, const float* fs_p, const float* var_p,
    const float* init_freqs, const float* alpha_p, const float* beta_p,
    const float* fe_w1, const float* fe_b1, const float* fe_w2, const float* fe_b2,
    const float* pr_w1, const float* pr_b1, const float* pr_w2, const float* pr_b2,
    const float* pr_w3, const float* pr_b3, const float* iter_w, const int* iter_p,
    float* out_eIF, float* out_xm, float* out_ym, float* out_scal)
{
    __shared__ float bufA[NN];   // cos  -> xs solution
    __shared__ float bufB[NN];   // sin  -> ys solution
    __shared__ float bufC[NN];   // MLP scratch -> new_eIF staging
    __shared__ double warpoff[16];
    __shared__ __align__(16) float sredAX[8], sredBX[8], sredAY[8], sredBY[8];
    __shared__ __align__(16) float sredSA[16], sredSB[16], sredF[16];
    __shared__ float eXLo[8][4],  eXHi[8][4];
    __shared__ float eYLo[8][4],  eYHi[8][4];
    __shared__ float eSLo[16][4], eSHi[16][4];
    __shared__ float sAB[4];     // [na, nb, betathr, bt]

    const int row = blockIdx.x, t = threadIdx.x;
    const int b = row / KK, ro = row*NN, bo = b*NN;
    const float dxf = 1.0f / (*fs_p);

    if (t < 256) {
        // ---- phase half (warps 0-7) ----
        double P[8];
        cumtz<256, 3>(t, eIF + ro, dxf, warpoff, P);
        int base = t*8;
        #pragma unroll
        for (int m = 0; m < 8; m++) {
            double frac = P[m] - floor(P[m]);
            float ph = (float)(frac * TWOPI_D);
            float sn, cs;
            __sincosf(ph, &sn, &cs);
            bufA[base+m] = cs;
            bufB[base+m] = sn;
        }
    } else {
        // ---- MLP half (warps 8-15, lt in 0..255) ----
        int lt = t - 256;
        float* m_avg = bufC;          // 8
        float* m_h1  = bufC + 8;      // 256  [b*32+j]
        float* m_h2  = bufC + 264;    // 144  [b*18+j]
        float* m_z1  = bufC + 408;    // 512  [b*64+j]
        float* m_z2  = bufC + 920;    // 256  [b*32+j]
        float* m_res = bufC + 1176;   // 16   [b*2+j]
        float alpha = *alpha_p, beta = *beta_p;
        if (lt == 0) {
            int it = *iter_p;
            sAB[3] = (float)pow(10.0, (double)it/36.0 - 10.0);
        }
        if (lt < BB) {
            float a = 0.f;
            #pragma unroll
            for (int k = 0; k < KK; k++) a += init_freqs[lt*KK + k];
            m_avg[lt] = a / (float)KK;
        }
        barx<4, 256>();
        {   // fe1: 8x32
            int bb2 = lt >> 5, j = lt & 31;
            float v = fe_w1[j]*m_avg[bb2] + fe_b1[j];
            m_h1[bb2*32 + j] = v > 0.f ? v : 0.f;
        }
        barx<4, 256>();
        if (lt < BB*16) { // fe2: 8x16
            int bb2 = lt >> 4, j = lt & 15;
            float acc = fe_b2[j];
            #pragma unroll
            for (int k = 0; k < 32; k++) acc += fe_w2[j*32 + k]*m_h1[bb2*32 + k];
            m_h2[bb2*18 + j] = acc > 0.f ? acc : 0.f;
        } else if (lt < BB*16 + BB) {
            int bb2 = lt - BB*16;
            m_h2[bb2*18 + 16] = alpha;
            m_h2[bb2*18 + 17] = beta;
        }
        barx<4, 256>();
        for (int idx = lt; idx < BB*64; idx += 256) { // pr1: 8x64
            int bb2 = idx >> 6, j = idx & 63;
            float acc = pr_b1[j];
            #pragma unroll
            for (int k = 0; k < 18; k++) acc += pr_w1[j*18 + k]*m_h2[bb2*18 + k];
            m_z1[bb2*64 + j] = acc > 0.f ? acc : 0.f;
        }
        barx<4, 256>();
        {   // pr2: 8x32
            int bb2 = lt >> 5, j = lt & 31;
            float acc = pr_b2[j];
            #pragma unroll
            for (int k = 0; k < 64; k++) acc += pr_w2[j*64 + k]*m_z1[bb2*64 + k];
            m_z2[bb2*32 + j] = acc > 0.f ? acc : 0.f;
        }
        barx<4, 256>();
        if (lt < BB*2) { // pr3 + tanh + scaling
            int bb2 = lt >> 1, j = lt & 1;
            float acc = pr_b3[j];
            #pragma unroll
            for (int k = 0; k < 32; k++) acc += pr_w3[j*32 + k]*m_z2[bb2*32 + k];
            float itf = (float)(*iter_p);
            float fac = 1.0f / (1.0f + expf(-(*iter_w)*itf));
            m_res[bb2*2 + j] = tanhf(acc) * fac * 0.1f;
        }
        barx<4, 256>();
        if (lt == 0) {
            float m0 = 0.f, m1 = 0.f;
            #pragma unroll
            for (int bb2 = 0; bb2 < BB; bb2++) { m0 += m_res[bb2*2]; m1 += m_res[bb2*2+1]; }
            m0 /= (float)BB; m1 /= (float)BB;
            float na = fminf(fmaxf(alpha + m0*alpha, 1e-6f), 0.01f);
            float nb = fminf(fmaxf(beta + m1*beta, 1e-6f), 0.1f);
            float bthr = fminf(sAB[3], nb);
            sAB[0] = na; sAB[1] = nb; sAB[2] = bthr;
            g_alpha = na;                     // same value from every block (benign)
            if (row == 0) { out_scal[0] = na; out_scal[1] = nb; }
        }
    }
    __syncthreads();

    const float na = sAB[0];
    const float bthr = sAB[2];

    // --- ||v|| for the norm-ball projection (u = scale*v) ---
    {
        float d0 = 0.f, d1 = 0.f;
        int b4 = t*4;
        #pragma unroll
        for (int m = 0; m < 4; m++) {
            int i = b4 + m;
            float v = s[bo+i] - sum_x[bo+i] - sum_y[bo+i] - lamuda[bo+i]/na;
            if (m & 1) d1 += v*v; else d0 += v*v;
        }
        float dd = warpRedux(d0 + d1);
        if ((t & 31) == 0) sredF[t >> 5] = dd;
    }
    __syncthreads();
    float n2 = sumP<16>(sredF);
    float nrm = sqrtf(n2);
    float e = sqrtf((float)NN * (*var_p));
    float scale = (nrm > e) ? (e / fmaxf(nrm, 1e-30f)) : 1.0f;

    // --- x/y CG setup (8 consecutive elems per thread within each half) ---
    const bool isY = (t >= 256);
    const int lt = t & 255;
    float dreg[8], rhs[8], x0v[8], sol[8];
    {
        int base = lt*8;
        #pragma unroll
        for (int j = 0; j < 8; j++) {
            int i = base + j;
            float c = bufA[i], sn = bufB[i];
            float xmv = xm[ro+i], ymv = ym[ro+i];
            float v = s[bo+i] - sum_x[bo+i] - sum_y[bo+i] - lamuda[bo+i]/na;
            float u = scale * v;
            float resid = v - u + xmv*c + ymv*sn;
            if (!isY) {
                dreg[j] = c*c + CG_REG;  rhs[j] = c*resid;  x0v[j] = xmv;
                g_u[bo+i] = u;   // x-half covers all i; dup across k-CTAs identical
            } else {
                dreg[j] = sn*sn + CG_REG; rhs[j] = sn*resid; x0v[j] = ymv;
            }
        }
    }
    __syncthreads();   // bufA/bufB reads done before solutions overwrite them
    float coef = 2.0f / na;
    if (!isY)
        cg_reg<8,8,1,false>(lt, coef, dreg, rhs, x0v, sol, sredAX, sredBX, eXLo, eXHi);
    else
        cg_reg<8,8,2,false>(lt, coef, dreg, rhs, x0v, sol, sredAY, sredBY, eYLo, eYHi);
    {
        int base = lt*8;
        float* dst = isY ? bufB : bufA;
        #pragma unroll
        for (int j = 0; j < 8; j++) dst[base+j] = sol[j];
    }
    __syncthreads();

    // --- smooth CG (full block, 4 consecutive elems per thread) ---
    float dregS[4], rhsS[4], zero4[4], solS[4];
    {
        int base = t*4;
        const float TWOPIF = 6.2831853071795864769f;
        #pragma unroll
        for (int m = 0; m < 4; m++) {
            int i = base + m;
            float xv = bufA[i], yv = bufB[i];
            float xb = (i == 0)    ? (bufA[1]-bufA[0]) / dxf
                     : (i == NN-1) ? (bufA[NN-1]-bufA[NN-2]) / dxf
                     : (bufA[i+1]-bufA[i-1]) / (2.0f*dxf);
            float yb = (i == 0)    ? (bufB[1]-bufB[0]) / dxf
                     : (i == NN-1) ? (bufB[NN-1]-bufB[NN-2]) / dxf
                     : (bufB[i+1]-bufB[i-1]) / (2.0f*dxf);
            float denom = xv*xv + yv*yv + 1e-12f;
            rhsS[m]  = (xv*yb - yv*xb) / (denom * TWOPIF);
            dregS[m] = 1.0f + CG_REG;
            zero4[m] = 0.f;
        }
    }
    float coefS = 2.0f / bthr;
    cg_reg<4,16,0,true>(t, coefS, dregS, rhsS, zero4, solS, sredSA, sredSB, eSLo, eSHi);

    // --- epilogue: outputs + new-phase contributions ---
    bool active = (mode_mask[row] != 0);
    float maskf = active ? 1.0f : 0.0f;
    float nxm[4], nym[4];
    {
        int base = t*4;
        #pragma unroll
        for (int m = 0; m < 4; m++) {
            int i = base + m;
            float ne = active ? (eIF[ro+i] - 0.5f*solS[m]) : eIF[ro+i];
            out_eIF[ro+i] = ne;
            nxm[m] = active ? bufA[i] : xm[ro+i];
            nym[m] = active ? bufB[i] : ym[ro+i];
            out_xm[ro+i] = nxm[m];
            out_ym[ro+i] = nym[m];
            bufC[i] = ne;
        }
    }
    __syncthreads();
    double P2[4];
    cumtz<512, 0>(t, bufC, dxf, warpoff, P2);
    {
        int base = t*4;
        #pragma unroll
        for (int m = 0; m < 4; m++) {
            int i = base + m;
            double frac = P2[m] - floor(P2[m]);
            float ph = (float)(frac * TWOPI_D);
            float sn, cs;
            __sincosf(ph, &sn, &cs);
            g_cx[ro+i] = maskf * nxm[m] * cs;
            g_cy[ro+i] = maskf * nym[m] * sn;
        }
    }
}

// ---------------- K2: bsx/bsy sums over K + new lamuda (64 blocks) ----------------
__global__ void __launch_bounds__(TM) final_kernel(
    const float* s, const float* lamuda, float* out_bsx, float* out_bsy, float* out_lam)
{
    int b = blockIdx.x >> 3, seg = blockIdx.x & 7, t = threadIdx.x;
    int i = seg*TM + t;
    float na = g_alpha;
    float bx = 0.f, by = 0.f;
    #pragma unroll
    for (int k = 0; k < KK; k++) {
        bx += g_cx[(b*KK + k)*NN + i];
        by += g_cy[(b*KK + k)*NN + i];
    }
    out_bsx[b*NN + i] = bx;
    out_bsy[b*NN + i] = by;
    out_lam[b*NN + i] = lamuda[b*NN + i] + na * (g_u[b*NN + i] + bx + by - s[b*NN + i]);
}

// ---------------- launch ----------------
extern "C" void kernel_launch(void* const* d_in, const int* in_sizes, int n_in,
                              void* d_out, int out_size) {
    const float* s          = (const float*)d_in[0];
    const float* eIF        = (const float*)d_in[1];
    const float* xm         = (const float*)d_in[2];
    const float* ym         = (const float*)d_in[3];
    const float* sum_x      = (const float*)d_in[4];
    const float* sum_y      = (const float*)d_in[5];
    const float* lamuda     = (const float*)d_in[6];
    const float* init_freqs = (const float*)d_in[7];
    const int*   mode_mask  = (const int*)d_in[8];
    const float* alpha      = (const float*)d_in[9];
    const float* beta       = (const float*)d_in[10];
    const float* var        = (const float*)d_in[11];
    const float* fs         = (const float*)d_in[12];
    const int*   iteration  = (const int*)d_in[13];
    const float* fe_w1      = (const float*)d_in[14];
    const float* fe_b1      = (const float*)d_in[15];
    const float* fe_w2      = (const float*)d_in[16];
    const float* fe_b2      = (const float*)d_in[17];
    const float* pr_w1      = (const float*)d_in[18];
    const float* pr_b1      = (const float*)d_in[19];
    const float* pr_w2      = (const float*)d_in[20];
    const float* pr_b2      = (const float*)d_in[21];
    const float* pr_w3      = (const float*)d_in[22];
    const float* pr_b3      = (const float*)d_in[23];
    const float* iter_w     = (const float*)d_in[24];

    float* out = (float*)d_out;
    const int BKN = NBK * NN;   // 65536
    const int BN  = BB * NN;    // 16384
    float* o_eIF  = out;
    float* o_xm   = out + BKN;
    float* o_ym   = out + 2*BKN;
    float* o_bsx  = out + 3*BKN;
    float* o_bsy  = o_bsx + BN;
    float* o_lam  = o_bsy + BN;
    float* o_scal = o_lam + BN;   // [new_alpha, new_beta]

    row_kernel<<<NBK, NT>>>(s, eIF, xm, ym, sum_x, sum_y, lamuda, mode_mask,
                            fs, var, init_freqs, alpha, beta,
                            fe_w1, fe_b1, fe_w2, fe_b2,
                            pr_w1, pr_b1, pr_w2, pr_b2, pr_w3, pr_b3,
                            iter_w, iteration,
                            o_eIF, o_xm, o_ym, o_scal);
    final_kernel<<<BB*8, TM>>>(s, lamuda, o_bsx, o_bsy, o_lam);
}

// round 15
// speedup vs baseline: 1.6449x; 1.0028x over previous
#include <cuda_runtime.h>
#include <cuda_bf16.h>
#include <math.h>

// Problem dims (fixed for this instance)
#define NN   2048
#define BB   8
#define KK   4
#define NBK  (BB*KK)      // 32
#define NT   512          // fused row kernel block size
#define CG_REG 1e-6f
#define TWOPI_D 6.283185307179586

// ---------------- scratch (device globals; no allocations allowed) ----------------
__device__ float g_cx[NBK*NN];
__device__ float g_cy[NBK*NN];
__device__ float g_u[BB*NN];
__device__ unsigned g_tick[BB];   // per-batch arrival counter (wraps mod 4 per call)

// ---------------- helpers ----------------
// Warp all-reduce: 5-level shfl butterfly (redux.sync.add.f32 NOT supported on sm_103).
__device__ __forceinline__ float warpRedux(float v) {
    #pragma unroll
    for (int o = 16; o > 0; o >>= 1) v += __shfl_xor_sync(0xffffffffu, v, o);
    return v;
}

// Sum NW floats (NW multiple of 4) from 16B-aligned smem via float4 loads.
template<int NW>
__device__ __forceinline__ float sumP(const float* s) {
    float acc = 0.f;
    #pragma unroll
    for (int k = 0; k < NW/4; k++) {
        float4 v = reinterpret_cast<const float4*>(s)[k];
        acc += (v.x + v.y) + (v.z + v.w);
    }
    return acc;
}

template<int BARID, int NTHR>
__device__ __forceinline__ void barx() {
    asm volatile("bar.sync %0, %1;" :: "n"(BARID), "n"(NTHR) : "memory");
}

// Pentadiagonal opedoub apply on register-resident p (EPT consecutive elems per
// thread). Neighbors via intra-warp shfl; warp-edge values supplied in hl/hr.
template<int EPT>
__device__ __forceinline__ void stencil_apply(const float p[EPT],
    float hl0, float hl1, float hr0, float hr1,
    bool lane0, bool lane31, bool firstT, bool lastT, float st[EPT])
{
    float lm2 = __shfl_up_sync(0xffffffffu, p[EPT-2], 1);
    float lm1 = __shfl_up_sync(0xffffffffu, p[EPT-1], 1);
    float rp0 = __shfl_down_sync(0xffffffffu, p[0], 1);
    float rp1 = __shfl_down_sync(0xffffffffu, p[1], 1);
    if (lane0)  { lm2 = hl0; lm1 = hl1; }
    if (lane31) { rp0 = hr0; rp1 = hr1; }
    float wb[EPT+4];
    wb[0] = lm2; wb[1] = lm1;
    #pragma unroll
    for (int j = 0; j < EPT; j++) wb[2+j] = p[j];
    wb[EPT+2] = rp0; wb[EPT+3] = rp1;
    #pragma unroll
    for (int j = 0; j < EPT; j++)
        st[j] = wb[j] - 4.0f*wb[j+1] + 6.0f*wb[j+2] - 4.0f*wb[j+3] + wb[j+4];
    if (firstT) {
        st[0] =  2.0f*p[0] - 3.0f*p[1] + p[2];
        st[1] = -3.0f*p[0] + 6.0f*p[1] - 4.0f*p[2] + p[3];
    }
    if (lastT) {
        st[EPT-2] = p[EPT-4] - 4.0f*p[EPT-3] + 6.0f*p[EPT-2] - 3.0f*p[EPT-1];
        st[EPT-1] = p[EPT-3] - 3.0f*p[EPT-2] + 2.0f*p[EPT-1];
    }
}

// Register-resident CG for (coef*opedoub + diag(dreg)) x = rhs over NW warps,
// EPT consecutive elements per thread (EPT<=8: register-budget ceiling,
// EPT=16 spills -- verified R11). 2 barriers/iter; explicit rsnew reduction
// (one-barrier recurrence cancels catastrophically -- verified R8).
// edge slots: [0,1] = one-time x0 halos; [2,3] = per-iteration r halos
// (consecutive uses separated by >=2 barriers -> race-free).
template<int EPT, int NW, int BARID, bool X0Z>
__device__ void cg_reg(int lt, float coef, const float dreg[EPT],
                       const float rhs[EPT], const float x0[EPT], float xout[EPT],
                       float* sredA, float* sredB,
                       float (*edgeLo)[4], float (*edgeHi)[4])
{
    constexpr int NTHR = NW*32;
    const int lane = lt & 31, w = lt >> 5;
    const bool lane0 = (lane == 0), lane31 = (lane == 31);
    const bool firstT = (lt == 0), lastT = (lt == NTHR-1);
    float p[EPT], r[EPT], x[EPT];
    float hl0 = 0.f, hl1 = 0.f, hr0 = 0.f, hr1 = 0.f;
    float rsold;
    bool done = false;

    if (X0Z) {
        float d0 = 0.f, d1 = 0.f;
        #pragma unroll
        for (int j = 0; j < EPT; j++) {
            r[j] = rhs[j]; p[j] = rhs[j]; x[j] = 0.f;
            if (j & 1) d1 += r[j]*r[j]; else d0 += r[j]*r[j];
        }
        if (lane0)  { edgeLo[w][2] = r[0];     edgeLo[w][3] = r[1]; }
        if (lane31) { edgeHi[w][2] = r[EPT-2]; edgeHi[w][3] = r[EPT-1]; }
        float dd = warpRedux(d0 + d1);
        if (lane0) sredB[w] = dd;
        barx<BARID, NTHR>();
        rsold = sumP<NW>(sredB);
        if (lane0  && w > 0)    { hl0 = edgeHi[w-1][2]; hl1 = edgeHi[w-1][3]; }
        if (lane31 && w < NW-1) { hr0 = edgeLo[w+1][2]; hr1 = edgeLo[w+1][3]; }
    } else {
        #pragma unroll
        for (int j = 0; j < EPT; j++) { p[j] = x0[j]; x[j] = x0[j]; }
        if (lane0)  { edgeLo[w][0] = p[0];     edgeLo[w][1] = p[1]; }
        if (lane31) { edgeHi[w][0] = p[EPT-2]; edgeHi[w][1] = p[EPT-1]; }
        barx<BARID, NTHR>();
        if (lane0  && w > 0)    { hl0 = edgeHi[w-1][0]; hl1 = edgeHi[w-1][1]; }
        if (lane31 && w < NW-1) { hr0 = edgeLo[w+1][0]; hr1 = edgeLo[w+1][1]; }
        float st[EPT];
        stencil_apply<EPT>(p, hl0, hl1, hr0, hr1, lane0, lane31, firstT, lastT, st);
        float d0 = 0.f, d1 = 0.f;
        #pragma unroll
        for (int j = 0; j < EPT; j++) {
            r[j] = rhs[j] - (coef*st[j] + dreg[j]*p[j]);
            if (j & 1) d1 += r[j]*r[j]; else d0 += r[j]*r[j];
            p[j] = r[j];
        }
        if (lane0)  { edgeLo[w][2] = r[0];     edgeLo[w][3] = r[1]; }
        if (lane31) { edgeHi[w][2] = r[EPT-2]; edgeHi[w][3] = r[EPT-1]; }
        float dd = warpRedux(d0 + d1);
        if (lane0) sredB[w] = dd;
        barx<BARID, NTHR>();
        rsold = sumP<NW>(sredB);
        if (lane0  && w > 0)    { hl0 = edgeHi[w-1][2]; hl1 = edgeHi[w-1][3]; }
        if (lane31 && w < NW-1) { hr0 = edgeLo[w+1][2]; hr1 = edgeLo[w+1][3]; }
    }

    for (int it = 0; it < 30; it++) {
        float st[EPT], Ap[EPT];
        stencil_apply<EPT>(p, hl0, hl1, hr0, hr1, lane0, lane31, firstT, lastT, st);
        float d0 = 0.f, d1 = 0.f;
        #pragma unroll
        for (int j = 0; j < EPT; j++) {
            Ap[j] = coef*st[j] + dreg[j]*p[j];
            if (j & 1) d1 += p[j]*Ap[j]; else d0 += p[j]*Ap[j];
        }
        float dd = warpRedux(d0 + d1);
        if (lane0) sredA[w] = dd;
        barx<BARID, NTHR>();
        float pAp = sumP<NW>(sredA);
        float a = __fdividef(rsold, pAp + 1e-12f);
        if (!done) {
            #pragma unroll
            for (int j = 0; j < EPT; j++) { x[j] += a*p[j]; r[j] -= a*Ap[j]; }
        }
        float e0 = 0.f, e1 = 0.f;
        #pragma unroll
        for (int j = 0; j < EPT; j++) {
            if (j & 1) e1 += r[j]*r[j]; else e0 += r[j]*r[j];
        }
        float dd2 = warpRedux(e0 + e1);
        if (lane0)  { sredB[w] = dd2; edgeLo[w][2] = r[0]; edgeLo[w][3] = r[1]; }
        if (lane31) { edgeHi[w][2] = r[EPT-2]; edgeHi[w][3] = r[EPT-1]; }
        barx<BARID, NTHR>();
        float rsnew = sumP<NW>(sredB);
        bool done1 = done || (rsnew < 1e-12f);   // == sqrt(rsnew) < 1e-6
        float bta = __fdividef(rsnew, rsold + 1e-12f);
        if (!done1) {
            #pragma unroll
            for (int j = 0; j < EPT; j++) p[j] = r[j] + bta*p[j];
            if (lane0  && w > 0)    { hl0 = edgeHi[w-1][2] + bta*hl0; hl1 = edgeHi[w-1][3] + bta*hl1; }
            if (lane31 && w < NW-1) { hr0 = edgeLo[w+1][2] + bta*hr0; hr1 = edgeLo[w+1][3] + bta*hr1; }
            rsold = rsnew;
        }
        done = done1;
    }
    #pragma unroll
    for (int j = 0; j < EPT; j++) xout[j] = x[j];
}

// cumulative trapezoid over NN with NTHR threads (NN/NTHR consecutive elems
// per thread), double accum, named barrier BARID (group-local).
template<int NTHR, int BARID>
__device__ void cumtz(int lt, const float* y, float dxf, double* warpoff, double* Pout) {
    constexpr int EPT2 = NN/NTHR, NW = NTHR/32;
    int lane = lt & 31, w = lt >> 5, base = lt*EPT2;
    double acc = 0.0, pre[EPT2];
    #pragma unroll
    for (int m = 0; m < EPT2; m++) {
        int j = base + m;
        float a = (j < NN-1) ? ((y[j] + y[j+1]) * (0.5f*dxf)) : 0.0f;
        pre[m] = acc; acc += (double)a;
    }
    double v = acc;
    #pragma unroll
    for (int o = 1; o < 32; o <<= 1) {
        double n = __shfl_up_sync(0xffffffffu, v, o);
        if (lane >= o) v += n;
    }
    if (lane == 31) warpoff[w] = v;
    double excl = v - acc;
    barx<BARID, NTHR>();
    if (lt == 0) {
        double run = 0.0;
        #pragma unroll
        for (int ww = 0; ww < NW; ww++) { double tmp = warpoff[ww]; warpoff[ww] = run; run += tmp; }
    }
    barx<BARID, NTHR>();
    double off = warpoff[w] + excl;
    #pragma unroll
    for (int m = 0; m < EPT2; m++) Pout[m] = off + pre[m];
}

// ---------------- K1: fully fused per-row pipeline ----------------
// 32 blocks x 512 threads.
// warps 0-7:  phase cumtrapz(eIF) -> cos/sin (named bar 3)
// warps 8-15: hyperparameter MLP (identical in every block; named bar 4)
// then: u projection -> concurrent x/y CG (256 thr each, bars 1/2) ->
// smooth CG (512 thr, bar 0) -> epilogue -> last CTA per batch does
// bsx/bsy/lamuda (ticket via g_tick, no second kernel).
__global__ void __launch_bounds__(NT) row_kernel(
    const float* s, const float* eIF, const float* xm, const float* ym,
    const float* sum_x, const float* sum_y, const float* lamuda,
    const int* mode_mask, const float* fs_p, const float* var_p,
    const float* init_freqs, const float* alpha_p, const float* beta_p,
    const float* fe_w1, const float* fe_b1, const float* fe_w2, const float* fe_b2,
    const float* pr_w1, const float* pr_b1, const float* pr_w2, const float* pr_b2,
    const float* pr_w3, const float* pr_b3, const float* iter_w, const int* iter_p,
    float* out_eIF, float* out_xm, float* out_ym,
    float* out_bsx, float* out_bsy, float* out_lam, float* out_scal)
{
    __shared__ float bufA[NN];   // cos  -> xs solution
    __shared__ float bufB[NN];   // sin  -> ys solution
    __shared__ float bufC[NN];   // MLP scratch -> new_eIF staging
    __shared__ double warpoff[16];
    __shared__ __align__(16) float sredAX[8], sredBX[8], sredAY[8], sredBY[8];
    __shared__ __align__(16) float sredSA[16], sredSB[16], sredF[16];
    __shared__ float eXLo[8][4],  eXHi[8][4];
    __shared__ float eYLo[8][4],  eYHi[8][4];
    __shared__ float eSLo[16][4], eSHi[16][4];
    __shared__ float sAB[4];     // [na, nb, betathr, bt]
    __shared__ int   isLast;

    const int row = blockIdx.x, t = threadIdx.x;
    const int b = row / KK, ro = row*NN, bo = b*NN;
    const float dxf = 1.0f / (*fs_p);

    if (t < 256) {
        // ---- phase half (warps 0-7) ----
        double P[8];
        cumtz<256, 3>(t, eIF + ro, dxf, warpoff, P);
        int base = t*8;
        #pragma unroll
        for (int m = 0; m < 8; m++) {
            double frac = P[m] - floor(P[m]);
            float ph = (float)(frac * TWOPI_D);
            float sn, cs;
            __sincosf(ph, &sn, &cs);
            bufA[base+m] = cs;
            bufB[base+m] = sn;
        }
    } else {
        // ---- MLP half (warps 8-15, lt in 0..255) ----
        int lt = t - 256;
        float* m_avg = bufC;          // 8
        float* m_h1  = bufC + 8;      // 256  [b*32+j]
        float* m_h2  = bufC + 264;    // 144  [b*18+j]
        float* m_z1  = bufC + 408;    // 512  [b*64+j]
        float* m_z2  = bufC + 920;    // 256  [b*32+j]
        float* m_res = bufC + 1176;   // 16   [b*2+j]
        float alpha = *alpha_p, beta = *beta_p;
        if (lt == 0) {
            int it = *iter_p;
            sAB[3] = (float)pow(10.0, (double)it/36.0 - 10.0);
        }
        if (lt < BB) {
            float a = 0.f;
            #pragma unroll
            for (int k = 0; k < KK; k++) a += init_freqs[lt*KK + k];
            m_avg[lt] = a / (float)KK;
        }
        barx<4, 256>();
        {   // fe1: 8x32
            int bb2 = lt >> 5, j = lt & 31;
            float v = fe_w1[j]*m_avg[bb2] + fe_b1[j];
            m_h1[bb2*32 + j] = v > 0.f ? v : 0.f;
        }
        barx<4, 256>();
        if (lt < BB*16) { // fe2: 8x16
            int bb2 = lt >> 4, j = lt & 15;
            float acc = fe_b2[j];
            #pragma unroll
            for (int k = 0; k < 32; k++) acc += fe_w2[j*32 + k]*m_h1[bb2*32 + k];
            m_h2[bb2*18 + j] = acc > 0.f ? acc : 0.f;
        } else if (lt < BB*16 + BB) {
            int bb2 = lt - BB*16;
            m_h2[bb2*18 + 16] = alpha;
            m_h2[bb2*18 + 17] = beta;
        }
        barx<4, 256>();
        for (int idx = lt; idx < BB*64; idx += 256) { // pr1: 8x64
            int bb2 = idx >> 6, j = idx & 63;
            float acc = pr_b1[j];
            #pragma unroll
            for (int k = 0; k < 18; k++) acc += pr_w1[j*18 + k]*m_h2[bb2*18 + k];
            m_z1[bb2*64 + j] = acc > 0.f ? acc : 0.f;
        }
        barx<4, 256>();
        {   // pr2: 8x32
            int bb2 = lt >> 5, j = lt & 31;
            float acc = pr_b2[j];
            #pragma unroll
            for (int k = 0; k < 64; k++) acc += pr_w2[j*64 + k]*m_z1[bb2*64 + k];
            m_z2[bb2*32 + j] = acc > 0.f ? acc : 0.f;
        }
        barx<4, 256>();
        if (lt < BB*2) { // pr3 + tanh + scaling
            int bb2 = lt >> 1, j = lt & 1;
            float acc = pr_b3[j];
            #pragma unroll
            for (int k = 0; k < 32; k++) acc += pr_w3[j*32 + k]*m_z2[bb2*32 + k];
            float itf = (float)(*iter_p);
            float fac = 1.0f / (1.0f + expf(-(*iter_w)*itf));
            m_res[bb2*2 + j] = tanhf(acc) * fac * 0.1f;
        }
        barx<4, 256>();
        if (lt == 0) {
            float m0 = 0.f, m1 = 0.f;
            #pragma unroll
            for (int bb2 = 0; bb2 < BB; bb2++) { m0 += m_res[bb2*2]; m1 += m_res[bb2*2+1]; }
            m0 /= (float)BB; m1 /= (float)BB;
            float na = fminf(fmaxf(alpha + m0*alpha, 1e-6f), 0.01f);
            float nb = fminf(fmaxf(beta + m1*beta, 1e-6f), 0.1f);
            float bthr = fminf(sAB[3], nb);
            sAB[0] = na; sAB[1] = nb; sAB[2] = bthr;
            if (row == 0) { out_scal[0] = na; out_scal[1] = nb; }
        }
    }
    __syncthreads();

    const float na = sAB[0];
    const float bthr = sAB[2];

    // --- ||v|| for the norm-ball projection (u = scale*v) ---
    {
        float d0 = 0.f, d1 = 0.f;
        int b4 = t*4;
        #pragma unroll
        for (int m = 0; m < 4; m++) {
            int i = b4 + m;
            float v = s[bo+i] - sum_x[bo+i] - sum_y[bo+i] - lamuda[bo+i]/na;
            if (m & 1) d1 += v*v; else d0 += v*v;
        }
        float dd = warpRedux(d0 + d1);
        if ((t & 31) == 0) sredF[t >> 5] = dd;
    }
    __syncthreads();
    float n2 = sumP<16>(sredF);
    float nrm = sqrtf(n2);
    float e = sqrtf((float)NN * (*var_p));
    float scale = (nrm > e) ? (e / fmaxf(nrm, 1e-30f)) : 1.0f;

    // --- x/y CG setup (8 consecutive elems per thread within each half) ---
    const bool isY = (t >= 256);
    const int lt = t & 255;
    float dreg[8], rhs[8], x0v[8], sol[8];
    {
        int base = lt*8;
        #pragma unroll
        for (int j = 0; j < 8; j++) {
            int i = base + j;
            float c = bufA[i], sn = bufB[i];
            float xmv = xm[ro+i], ymv = ym[ro+i];
            float v = s[bo+i] - sum_x[bo+i] - sum_y[bo+i] - lamuda[bo+i]/na;
            float u = scale * v;
            float resid = v - u + xmv*c + ymv*sn;
            if (!isY) {
                dreg[j] = c*c + CG_REG;  rhs[j] = c*resid;  x0v[j] = xmv;
                g_u[bo+i] = u;   // x-half covers all i; dup across k-CTAs identical
            } else {
                dreg[j] = sn*sn + CG_REG; rhs[j] = sn*resid; x0v[j] = ymv;
            }
        }
    }
    __syncthreads();   // bufA/bufB reads done before solutions overwrite them
    float coef = 2.0f / na;
    if (!isY)
        cg_reg<8,8,1,false>(lt, coef, dreg, rhs, x0v, sol, sredAX, sredBX, eXLo, eXHi);
    else
        cg_reg<8,8,2,false>(lt, coef, dreg, rhs, x0v, sol, sredAY, sredBY, eYLo, eYHi);
    {
        int base = lt*8;
        float* dst = isY ? bufB : bufA;
        #pragma unroll
        for (int j = 0; j < 8; j++) dst[base+j] = sol[j];
    }
    __syncthreads();

    // --- smooth CG (full block, 4 consecutive elems per thread) ---
    float dregS[4], rhsS[4], zero4[4], solS[4];
    {
        int base = t*4;
        const float TWOPIF = 6.2831853071795864769f;
        #pragma unroll
        for (int m = 0; m < 4; m++) {
            int i = base + m;
            float xv = bufA[i], yv = bufB[i];
            float xb = (i == 0)    ? (bufA[1]-bufA[0]) / dxf
                     : (i == NN-1) ? (bufA[NN-1]-bufA[NN-2]) / dxf
                     : (bufA[i+1]-bufA[i-1]) / (2.0f*dxf);
            float yb = (i == 0)    ? (bufB[1]-bufB[0]) / dxf
                     : (i == NN-1) ? (bufB[NN-1]-bufB[NN-2]) / dxf
                     : (bufB[i+1]-bufB[i-1]) / (2.0f*dxf);
            float denom = xv*xv + yv*yv + 1e-12f;
            rhsS[m]  = (xv*yb - yv*xb) / (denom * TWOPIF);
            dregS[m] = 1.0f + CG_REG;
            zero4[m] = 0.f;
        }
    }
    float coefS = 2.0f / bthr;
    cg_reg<4,16,0,true>(t, coefS, dregS, rhsS, zero4, solS, sredSA, sredSB, eSLo, eSHi);

    // --- epilogue: outputs + new-phase contributions ---
    bool active = (mode_mask[row] != 0);
    float maskf = active ? 1.0f : 0.0f;
    float nxm[4], nym[4];
    {
        int base = t*4;
        #pragma unroll
        for (int m = 0; m < 4; m++) {
            int i = base + m;
            float ne = active ? (eIF[ro+i] - 0.5f*solS[m]) : eIF[ro+i];
            out_eIF[ro+i] = ne;
            nxm[m] = active ? bufA[i] : xm[ro+i];
            nym[m] = active ? bufB[i] : ym[ro+i];
            out_xm[ro+i] = nxm[m];
            out_ym[ro+i] = nym[m];
            bufC[i] = ne;
        }
    }
    __syncthreads();
    double P2[4];
    cumtz<512, 0>(t, bufC, dxf, warpoff, P2);
    {
        int base = t*4;
        #pragma unroll
        for (int m = 0; m < 4; m++) {
            int i = base + m;
            double frac = P2[m] - floor(P2[m]);
            float ph = (float)(frac * TWOPI_D);
            float sn, cs;
            __sincosf(ph, &sn, &cs);
            g_cx[ro+i] = maskf * nxm[m] * cs;
            g_cy[ro+i] = maskf * nym[m] * sn;
        }
    }

    // --- merged final: last-arriving CTA of each batch computes bsx/bsy/lamuda ---
    // Each thread fences its own g_cx/g_cy/g_u stores, then the CTA takes a
    // ticket. Counter is monotonic (wraps mod 4 per call: 4 CTAs per batch per
    // launch), so no reset kernel is needed and replays stay deterministic.
    __threadfence();
    __syncthreads();
    if (t == 0) {
        unsigned tk = atomicAdd(&g_tick[b], 1u);
        isLast = ((tk & 3u) == 3u) ? 1 : 0;
        __threadfence();   // acquire: order subsequent reads after the atomic
    }
    __syncthreads();
    if (isLast) {
        for (int i = t; i < NN; i += NT) {
            float bx = 0.f, by = 0.f;
            #pragma unroll
            for (int k = 0; k < KK; k++) {
                bx += g_cx[(b*KK + k)*NN + i];
                by += g_cy[(b*KK + k)*NN + i];
            }
            out_bsx[bo + i] = bx;
            out_bsy[bo + i] = by;
            out_lam[bo + i] = lamuda[bo + i] + na * (g_u[bo + i] + bx + by - s[bo + i]);
        }
    }
}

// ---------------- launch ----------------
extern "C" void kernel_launch(void* const* d_in, const int* in_sizes, int n_in,
                              void* d_out, int out_size) {
    const float* s          = (const float*)d_in[0];
    const float* eIF        = (const float*)d_in[1];
    const float* xm         = (const float*)d_in[2];
    const float* ym         = (const float*)d_in[3];
    const float* sum_x      = (const float*)d_in[4];
    const float* sum_y      = (const float*)d_in[5];
    const float* lamuda     = (const float*)d_in[6];
    const float* init_freqs = (const float*)d_in[7];
    const int*   mode_mask  = (const int*)d_in[8];
    const float* alpha      = (const float*)d_in[9];
    const float* beta       = (const float*)d_in[10];
    const float* var        = (const float*)d_in[11];
    const float* fs         = (const float*)d_in[12];
    const int*   iteration  = (const int*)d_in[13];
    const float* fe_w1      = (const float*)d_in[14];
    const float* fe_b1      = (const float*)d_in[15];
    const float* fe_w2      = (const float*)d_in[16];
    const float* fe_b2      = (const float*)d_in[17];
    const float* pr_w1      = (const float*)d_in[18];
    const float* pr_b1      = (const float*)d_in[19];
    const float* pr_w2      = (const float*)d_in[20];
    const float* pr_b2      = (const float*)d_in[21];
    const float* pr_w3      = (const float*)d_in[22];
    const float* pr_b3      = (const float*)d_in[23];
    const float* iter_w     = (const float*)d_in[24];

    float* out = (float*)d_out;
    const int BKN = NBK * NN;   // 65536
    const int BN  = BB * NN;    // 16384
    float* o_eIF  = out;
    float* o_xm   = out + BKN;
    float* o_ym   = out + 2*BKN;
    float* o_bsx  = out + 3*BKN;
    float* o_bsy  = o_bsx + BN;
    float* o_lam  = o_bsy + BN;
    float* o_scal = o_lam + BN;   // [new_alpha, new_beta]

    row_kernel<<<NBK, NT>>>(s, eIF, xm, ym, sum_x, sum_y, lamuda, mode_mask,
                            fs, var, init_freqs, alpha, beta,
                            fe_w1, fe_b1, fe_w2, fe_b2,
                            pr_w1, pr_b1, pr_w2, pr_b2, pr_w3, pr_b3,
                            iter_w, iteration,
                            o_eIF, o_xm, o_ym, o_bsx, o_bsy, o_lam, o_scal);
}